// round 9
// baseline (speedup 1.0000x reference)
#include <cuda_runtime.h>

#define BB 64
#define HH 512
#define LL 128
#define GRID 128
#define TPB 512

// persistent state
__device__ float g_ctx[(size_t)BB * LL * HH];  // [b][l][h]
__device__ float g_h[BB * HH];
__device__ float g_c[BB * HH];
__device__ float g_cat[BB * 2 * HH];           // [b][0:512]=hid, [512:1024]=h_t
__device__ float g_inp[BB * HH];
__device__ float g_mask[BB * LL];
__device__ float g_sc[BB * LL];
__device__ int   g_bidx[BB];

// distributed barrier flags; epochs persist across calls (base read at entry)
__device__ volatile unsigned g_arrive[GRID];

#define OUT_PTR  (BB * LL * LL)
#define OUT_H    (OUT_PTR + BB * LL)
#define OUT_C    (OUT_H + BB * HH)

__device__ __forceinline__ float wsum(float v) {
#pragma unroll
    for (int off = 16; off; off >>= 1) v += __shfl_xor_sync(0xffffffffu, v, off);
    return v;
}

__device__ __forceinline__ float fast_tanh(float x) {
    float e = __expf(2.0f * x);
    return 1.0f - __fdividef(2.0f, e + 1.0f);
}

// packed f32x2 FMA: d += a * b (elementwise)
__device__ __forceinline__ void ffma2(float2& d, float2 a, float2 b) {
    asm("{\n\t"
        ".reg .b64 ra, rb, rd;\n\t"
        "mov.b64 ra, {%2, %3};\n\t"
        "mov.b64 rb, {%4, %5};\n\t"
        "mov.b64 rd, {%0, %1};\n\t"
        "fma.rn.f32x2 rd, ra, rb, rd;\n\t"
        "mov.b64 {%0, %1}, rd;\n\t"
        "}"
        : "+f"(d.x), "+f"(d.y)
        : "f"(a.x), "f"(a.y), "f"(b.x), "f"(b.y));
}

// distributed grid barrier: every block polls all arrival flags (no release hop)
__device__ __forceinline__ void gbar(unsigned e) {
    __syncthreads();
    if (threadIdx.x == 0) {
        __threadfence();               // publish this block's phase writes (release)
        g_arrive[blockIdx.x] = e;
    }
    __syncthreads();
    if (threadIdx.x < GRID) {
        while (g_arrive[threadIdx.x] < e) { __nanosleep(20); }
    }
    __syncthreads();
    if (threadIdx.x == 0) __threadfence();   // acquire (IVALL: fresh L1)
    __syncthreads();
}

// cluster pair sync (blocks 2b, 2b+1)
__device__ __forceinline__ void csync() {
    __syncthreads();
    __threadfence();   // pair-visible via L2
    asm volatile("barrier.cluster.arrive.aligned;" ::: "memory");
    asm volatile("barrier.cluster.wait.aligned;" ::: "memory");
    __syncthreads();
}

// ---------------- single persistent kernel: init + ctx + 128 steps ----------------
__global__ __launch_bounds__(TPB, 1) __cluster_dims__(2, 1, 1) void k_all(
    const float* __restrict__ h0, const float* __restrict__ c0,
    const float* __restrict__ ctxin,
    const float* __restrict__ Wc, const float* __restrict__ bc,
    const float* __restrict__ Whh, const float* __restrict__ bhh,
    const float* __restrict__ Win, const float* __restrict__ bin,
    const float* __restrict__ Wout, const float* __restrict__ bout,
    const float* __restrict__ V, float* __restrict__ out) {
    __shared__ float xs[16 * 512];     // 32KB staging
    __shared__ float sm_inp[HH];
    __shared__ float sm_sc[LL];
    __shared__ float sm_alpha[LL];
    __shared__ float sm_mask[LL];
    __shared__ float sm_part[512];

    const int blk = blockIdx.x;
    const int tid = threadIdx.x, lane = tid & 31, w = tid >> 5;

    // base epoch: own flag equals final epoch of previous call (0 when cold)
    unsigned ep = g_arrive[blk];

    // ======== init phase ========
    {
        int gi = blk * TPB + tid;
        if (gi < BB * HH) { g_h[gi] = h0[gi]; g_c[gi] = c0[gi]; }
        if (gi < BB * LL) g_mask[gi] = 1.0f;
    }
    gbar(++ep);

    // ======== ctx precompute: ctx[b,l,h] = sum_d Wc[h,d]*ctxin[b,d,l] + bc[h] ========
#pragma unroll 1
    for (int sub = 0; sub < 2; sub++) {
        int v = blk + sub * GRID;
        int b = v >> 2, l0 = (v & 3) * 32;

        float2 acc[16];
#pragma unroll
        for (int p = 0; p < 16; p++) acc[p] = make_float2(0.f, 0.f);

        for (int dc = 0; dc < HH; dc += 128) {
            __syncthreads();
            for (int fi = tid; fi < 1024; fi += TPB) {
                int di = fi >> 3, lq = fi & 7;
                float4 val = __ldcg((const float4*)(ctxin +
                    ((size_t)b * HH + dc + di) * LL + l0 + lq * 4));
                *(float4*)&xs[di * 36 + lq * 4] = val;
            }
            __syncthreads();

            const float* wrow = Wc + (size_t)tid * HH + dc;
            for (int d4 = 0; d4 < 128; d4 += 4) {
                float4 wq = *(const float4*)(wrow + d4);
                float wv[4] = {wq.x, wq.y, wq.z, wq.w};
#pragma unroll
                for (int j = 0; j < 4; j++) {
                    float2 ws = make_float2(wv[j], wv[j]);
                    const float2* srow = (const float2*)&xs[(d4 + j) * 36];
#pragma unroll
                    for (int p = 0; p < 16; p++) ffma2(acc[p], ws, srow[p]);
                }
            }
        }
        float bcv = bc[tid];
#pragma unroll
        for (int p = 0; p < 16; p++) {
            size_t base = ((size_t)b * LL + l0 + 2 * p) * HH + tid;
            g_ctx[base] = acc[p].x + bcv;
            g_ctx[base + HH] = acc[p].y + bcv;
        }
    }
    gbar(++ep);

    // ======== step loop ========
    for (int t = 0; t < LL; t++) {
        // ---- Phase A: gates GEMM (f32x2) + LSTM cell ----
#pragma unroll 1
        for (int sub = 0; sub < 2; sub++) {
            int vt = blk + sub * GRID;
            int it = vt & 63, bt = vt >> 6;
            int ibase = it * 8, bbase = bt * 16;
            __syncthreads();
            {
                const float4* src = (const float4*)(g_h + bbase * HH);
                float4* dst = (float4*)xs;
                for (int idx = tid; idx < 16 * 512 / 4; idx += TPB)
                    dst[idx] = __ldcg(src + idx);
            }
            __syncthreads();

            int i = ibase + (w >> 1);
            int bh = (w & 1) * 8;
            const float* wr0 = Whh + (size_t)(0 * HH + i) * HH;
            const float* wr1 = Whh + (size_t)(1 * HH + i) * HH;
            const float* wr2 = Whh + (size_t)(2 * HH + i) * HH;
            const float* wr3 = Whh + (size_t)(3 * HH + i) * HH;

            float2 acc[4][8];
#pragma unroll
            for (int g = 0; g < 4; g++)
#pragma unroll
                for (int b = 0; b < 8; b++) acc[g][b] = make_float2(0.f, 0.f);

            float2 c0v = *(const float2*)(wr0 + lane * 2);
            float2 c1v = *(const float2*)(wr1 + lane * 2);
            float2 c2v = *(const float2*)(wr2 + lane * 2);
            float2 c3v = *(const float2*)(wr3 + lane * 2);
#pragma unroll
            for (int kk = 0; kk < 8; kk++) {
                float2 n0, n1, n2, n3;
                if (kk < 7) {
                    int kn = (kk + 1) * 64 + lane * 2;
                    n0 = *(const float2*)(wr0 + kn);
                    n1 = *(const float2*)(wr1 + kn);
                    n2 = *(const float2*)(wr2 + kn);
                    n3 = *(const float2*)(wr3 + kn);
                }
                int k = kk * 64 + lane * 2;
#pragma unroll
                for (int b = 0; b < 8; b++) {
                    float2 hv = *(const float2*)&xs[(bh + b) * 512 + k];
                    ffma2(acc[0][b], c0v, hv);
                    ffma2(acc[1][b], c1v, hv);
                    ffma2(acc[2][b], c2v, hv);
                    ffma2(acc[3][b], c3v, hv);
                }
                if (kk < 7) { c0v = n0; c1v = n1; c2v = n2; c3v = n3; }
            }

            float gate[4] = {0.f, 0.f, 0.f, 0.f};
#pragma unroll
            for (int g = 0; g < 4; g++)
#pragma unroll
                for (int b = 0; b < 8; b++) {
                    float vv = wsum(acc[g][b].x + acc[g][b].y);
                    if (lane == b) gate[g] = vv;
                }

            if (lane < 8) {
                int b = bbase + bh + lane;
                float ig = gate[0] + bhh[0 * HH + i];
                float fg = gate[1] + bhh[1 * HH + i];
                float gg = gate[2] + bhh[2 * HH + i];
                float og = gate[3] + bhh[3 * HH + i];
                float c_old = g_c[b * HH + i];
                float si = 1.f / (1.f + expf(-ig));
                float sf = 1.f / (1.f + expf(-fg));
                float so = 1.f / (1.f + expf(-og));
                float ct = sf * c_old + si * tanhf(gg);
                float ht = so * tanhf(ct);
                g_c[b * HH + i] = ct;
                g_cat[b * 2 * HH + HH + i] = ht;
            }
        }
        gbar(++ep);

        // ---- Phase B: inp = W_in * h_t + b_in (f32x2) ----
        {
            int rt = blk & 15, bt = blk >> 4;
            int bbase = bt * 8, r0 = rt * 32 + w * 2;
            for (int idx = tid; idx < 8 * 128; idx += TPB) {
                int b = idx >> 7, j = idx & 127;
                ((float4*)xs)[b * 128 + j] =
                    __ldcg((const float4*)(g_cat + (size_t)(bbase + b) * 2 * HH + HH) + j);
            }
            __syncthreads();

            const float* w0 = Win + (size_t)r0 * HH;
            const float* w1 = Win + (size_t)(r0 + 1) * HH;
            float2 acc[2][8];
#pragma unroll
            for (int r = 0; r < 2; r++)
#pragma unroll
                for (int b = 0; b < 8; b++) acc[r][b] = make_float2(0.f, 0.f);

            float2 a0 = *(const float2*)(w0 + lane * 2);
            float2 a1 = *(const float2*)(w1 + lane * 2);
#pragma unroll
            for (int kk = 0; kk < 8; kk++) {
                float2 na0, na1;
                if (kk < 7) {
                    int kn = (kk + 1) * 64 + lane * 2;
                    na0 = *(const float2*)(w0 + kn);
                    na1 = *(const float2*)(w1 + kn);
                }
                int k = kk * 64 + lane * 2;
#pragma unroll
                for (int b = 0; b < 8; b++) {
                    float2 xv = *(const float2*)&xs[b * 512 + k];
                    ffma2(acc[0][b], a0, xv);
                    ffma2(acc[1][b], a1, xv);
                }
                if (kk < 7) { a0 = na0; a1 = na1; }
            }

            float res[2] = {0.f, 0.f};
#pragma unroll
            for (int r = 0; r < 2; r++)
#pragma unroll
                for (int b = 0; b < 8; b++) {
                    float vv = wsum(acc[r][b].x + acc[r][b].y);
                    if (lane == b) res[r] = vv;
                }
            if (lane < 8) {
#pragma unroll
                for (int r = 0; r < 2; r++)
                    g_inp[(size_t)(bbase + lane) * HH + r0 + r] = res[r] + bin[r0 + r];
            }
        }
        gbar(++ep);

        // ---- Phase C1: scores (cluster pair: 2 blocks per batch, 64 l each) ----
        {
            int b = blk >> 1, half = blk & 1;
            sm_inp[tid] = __ldcg(&g_inp[b * HH + tid]);
            __syncthreads();

            float inpv[16], Vv[16];
#pragma unroll
            for (int m = 0; m < 16; m++) {
                inpv[m] = sm_inp[m * 32 + lane];
                Vv[m] = V[m * 32 + lane];
            }
#pragma unroll
            for (int li = 0; li < 4; li++) {
                int l = half * 64 + w * 4 + li;
                const float* cp = g_ctx + ((size_t)b * LL + l) * HH + lane;
                float s = 0.f;
#pragma unroll
                for (int m = 0; m < 16; m++) {
                    float cv = __ldcg(cp + m * 32);
                    s += Vv[m] * fast_tanh(inpv[m] + cv);
                }
                s = wsum(s);
                if (lane == 0) g_sc[b * LL + l] = s;
            }
        }
        csync();   // pair-local: both halves' scores visible

        // ---- Phase C2: softmax + argmax + hid (pair of blocks per batch) ----
        {
            int b = blk >> 1, half = blk & 1;
            if (tid < LL) {
                sm_sc[tid] = __ldcg(&g_sc[b * LL + tid]);
                sm_mask[tid] = __ldcg(&g_mask[b * LL + tid]);
            }
            __syncthreads();

            if (w == 0) {
                float sv[4], mk[4];
#pragma unroll
                for (int j = 0; j < 4; j++) {
                    mk[j] = sm_mask[lane + 32 * j];
                    sv[j] = (mk[j] != 0.f) ? sm_sc[lane + 32 * j] : -3.4e38f;
                }
                float m = fmaxf(fmaxf(sv[0], sv[1]), fmaxf(sv[2], sv[3]));
#pragma unroll
                for (int off = 16; off; off >>= 1)
                    m = fmaxf(m, __shfl_xor_sync(0xffffffffu, m, off));

                float e[4], sum = 0.f;
#pragma unroll
                for (int j = 0; j < 4; j++) {
                    e[j] = (mk[j] != 0.f) ? expf(sv[j] - m) : 0.f;
                    sum += e[j];
                }
                sum = wsum(sum);
                float inv = 1.f / sum;

                float best = -1.f;
                int bidx = 0;
#pragma unroll
                for (int j = 0; j < 4; j++) {
                    int l = lane + 32 * j;
                    float a = e[j] * inv;
                    sm_alpha[l] = a;
                    if (half == 0)
                        out[(size_t)b * LL * LL + (size_t)t * LL + l] = a;
                    float cand = (mk[j] != 0.f) ? a : -1.f;
                    if (cand > best) { best = cand; bidx = l; }
                }
#pragma unroll
                for (int off = 16; off; off >>= 1) {
                    float ob = __shfl_xor_sync(0xffffffffu, best, off);
                    int oi = __shfl_xor_sync(0xffffffffu, bidx, off);
                    if (ob > best || (ob == best && oi < bidx)) { best = ob; bidx = oi; }
                }
                if (half == 0 && lane == 0) {
                    out[OUT_PTR + b * LL + t] = (float)bidx;
                    g_bidx[b] = bidx;
                }
            }
            __syncthreads();

            {
                int lh = tid >> 8;
                int hh = half * 256 + (tid & 255);
                const float* cp = g_ctx + (size_t)b * LL * HH + (size_t)(lh * 64) * HH + hh;
                float a = 0.f;
#pragma unroll 8
                for (int l = 0; l < 64; l++)
                    a += __ldcg(cp + (size_t)l * HH) * sm_alpha[lh * 64 + l];
                sm_part[tid] = a;
            }
            __syncthreads();
            if (tid < 256)
                g_cat[b * 2 * HH + half * 256 + tid] = sm_part[tid] + sm_part[256 + tid];
        }
        gbar(++ep);

        // ---- Phase D: h = tanh(W_out * [hid, h_t] + b_out) + mask update ----
        {
            if (blk == 0 && tid < BB)
                g_mask[tid * LL + __ldcg(&g_bidx[tid])] = 0.f;

            int rt = blk & 15, bt = blk >> 4;
            int bbase = bt * 8, r0 = rt * 32 + w * 2;
            {
                const float4* src = (const float4*)(g_cat + (size_t)bbase * 2 * HH);
                float4* dst = (float4*)xs;
                for (int idx = tid; idx < 8 * 1024 / 4; idx += TPB)
                    dst[idx] = __ldcg(src + idx);
            }
            __syncthreads();

            const float* w0 = Wout + (size_t)r0 * 2 * HH;
            const float* w1 = Wout + (size_t)(r0 + 1) * 2 * HH;
            float2 acc[2][8];
#pragma unroll
            for (int r = 0; r < 2; r++)
#pragma unroll
                for (int b = 0; b < 8; b++) acc[r][b] = make_float2(0.f, 0.f);

            float2 a0 = *(const float2*)(w0 + lane * 2);
            float2 a1 = *(const float2*)(w1 + lane * 2);
#pragma unroll
            for (int kk = 0; kk < 16; kk++) {
                float2 na0, na1;
                if (kk < 15) {
                    int kn = (kk + 1) * 64 + lane * 2;
                    na0 = *(const float2*)(w0 + kn);
                    na1 = *(const float2*)(w1 + kn);
                }
                int k = kk * 64 + lane * 2;
#pragma unroll
                for (int b = 0; b < 8; b++) {
                    float2 xv = *(const float2*)&xs[b * 1024 + k];
                    ffma2(acc[0][b], a0, xv);
                    ffma2(acc[1][b], a1, xv);
                }
                if (kk < 15) { a0 = na0; a1 = na1; }
            }

            float res[2] = {0.f, 0.f};
#pragma unroll
            for (int r = 0; r < 2; r++)
#pragma unroll
                for (int b = 0; b < 8; b++) {
                    float vv = wsum(acc[r][b].x + acc[r][b].y);
                    if (lane == b) res[r] = vv;
                }
            if (lane < 8) {
#pragma unroll
                for (int r = 0; r < 2; r++)
                    g_h[(size_t)(bbase + lane) * HH + r0 + r] =
                        tanhf(res[r] + bout[r0 + r]);
            }
        }
        gbar(++ep);
    }

    // final h/c copy
    for (int i = blk * TPB + tid; i < BB * HH; i += GRID * TPB) {
        out[OUT_H + i] = g_h[i];
        out[OUT_C + i] = g_c[i];
    }
}

extern "C" void kernel_launch(void* const* d_in, const int* in_sizes, int n_in,
                              void* d_out, int out_size) {
    const float* h0   = (const float*)d_in[2];
    const float* c0   = (const float*)d_in[3];
    const float* ctxi = (const float*)d_in[4];
    const float* Whh  = (const float*)d_in[5];
    const float* bhh  = (const float*)d_in[6];
    const float* Win  = (const float*)d_in[7];
    const float* bin  = (const float*)d_in[8];
    const float* Wc   = (const float*)d_in[9];
    const float* bc   = (const float*)d_in[10];
    const float* V    = (const float*)d_in[11];
    const float* Wout = (const float*)d_in[12];
    const float* bout = (const float*)d_in[13];
    float* out = (float*)d_out;

    k_all<<<GRID, TPB>>>(h0, c0, ctxi, Wc, bc, Whh, bhh,
                         Win, bin, Wout, bout, V, out);
}

// round 11
// speedup vs baseline: 1.4658x; 1.4658x over previous
#include <cuda_runtime.h>

#define BB 64
#define HH 512
#define LL 128
#define GRID 128
#define TPB 512

// persistent state
__device__ float g_ctx[(size_t)BB * LL * HH];  // [b][l][h]
__device__ float g_h[BB * HH];
__device__ float g_c[BB * HH];
__device__ float g_cat[BB * 2 * HH];           // [b][0:512]=hid, [512:1024]=h_t
__device__ float g_inp[BB * HH];
__device__ float g_mask[BB * LL];
__device__ float g_sc[BB * LL];
__device__ int   g_bidx[BB];

// hub barrier state; epochs persist across calls (base read at entry)
__device__ volatile unsigned g_arrive[GRID];
__device__ volatile unsigned g_rel;

#define OUT_PTR  (BB * LL * LL)
#define OUT_H    (OUT_PTR + BB * LL)
#define OUT_C    (OUT_H + BB * HH)

__device__ __forceinline__ float wsum(float v) {
#pragma unroll
    for (int off = 16; off; off >>= 1) v += __shfl_xor_sync(0xffffffffu, v, off);
    return v;
}

__device__ __forceinline__ float fast_tanh(float x) {
    float e = __expf(2.0f * x);
    return 1.0f - __fdividef(2.0f, e + 1.0f);
}

// packed f32x2 FMA: d += a * b (elementwise)
__device__ __forceinline__ void ffma2(float2& d, float2 a, float2 b) {
    asm("{\n\t"
        ".reg .b64 ra, rb, rd;\n\t"
        "mov.b64 ra, {%2, %3};\n\t"
        "mov.b64 rb, {%4, %5};\n\t"
        "mov.b64 rd, {%0, %1};\n\t"
        "fma.rn.f32x2 rd, ra, rb, rd;\n\t"
        "mov.b64 {%0, %1}, rd;\n\t"
        "}"
        : "+f"(d.x), "+f"(d.y)
        : "f"(a.x), "f"(a.y), "f"(b.x), "f"(b.y));
}

// hub grid barrier. Release fence on arrival orders phase writes to L2.
// NO acquire fence: all cross-block data reads use __ldcg (L2 = coherence
// point), so we avoid the CCTL.IVALL L1 flush and keep weights L1-resident.
__device__ __forceinline__ void gbar(unsigned e) {
    __syncthreads();
    if (threadIdx.x == 0) {
        __threadfence();               // release: publish phase writes
        g_arrive[blockIdx.x] = e;
    }
    if (blockIdx.x == 0) {
        if (threadIdx.x < GRID) {
            while (g_arrive[threadIdx.x] < e) { __nanosleep(20); }
        }
        __syncthreads();
        if (threadIdx.x == 0) g_rel = e;
    }
    if (threadIdx.x == 0) {
        while (g_rel < e) { __nanosleep(20); }
    }
    __syncthreads();
}

// cluster pair sync (blocks 2b, 2b+1); arrive/wait carry release/acquire
__device__ __forceinline__ void csync() {
    __syncthreads();
    asm volatile("barrier.cluster.arrive.aligned;" ::: "memory");
    asm volatile("barrier.cluster.wait.aligned;" ::: "memory");
    __syncthreads();
}

// ---------------- single persistent kernel: init + ctx + 128 steps ----------------
__global__ __launch_bounds__(TPB, 1) __cluster_dims__(2, 1, 1) void k_all(
    const float* __restrict__ h0, const float* __restrict__ c0,
    const float* __restrict__ ctxin,
    const float* __restrict__ Wc, const float* __restrict__ bc,
    const float* __restrict__ Whh, const float* __restrict__ bhh,
    const float* __restrict__ Win, const float* __restrict__ bin,
    const float* __restrict__ Wout, const float* __restrict__ bout,
    const float* __restrict__ V, float* __restrict__ out) {
    __shared__ float xs[16 * 512];     // 32KB staging
    __shared__ float sm_inp[HH];
    __shared__ float sm_sc[LL];
    __shared__ float sm_alpha[LL];
    __shared__ float sm_mask[LL];
    __shared__ float sm_part[512];

    const int blk = blockIdx.x;
    const int tid = threadIdx.x, lane = tid & 31, w = tid >> 5;

    // base epoch from previous call (0 when cold)
    unsigned ep = g_rel;

    // ======== init phase ========
    {
        int gi = blk * TPB + tid;
        if (gi < BB * HH) { g_h[gi] = h0[gi]; g_c[gi] = c0[gi]; }
        if (gi < BB * LL) g_mask[gi] = 1.0f;
    }
    gbar(++ep);

    // ======== ctx precompute: ctx[b,l,h] = sum_d Wc[h,d]*ctxin[b,d,l] + bc[h] ========
#pragma unroll 1
    for (int sub = 0; sub < 2; sub++) {
        int v = blk + sub * GRID;
        int b = v >> 2, l0 = (v & 3) * 32;

        float2 acc[16];
#pragma unroll
        for (int p = 0; p < 16; p++) acc[p] = make_float2(0.f, 0.f);

        for (int dc = 0; dc < HH; dc += 128) {
            __syncthreads();
            for (int fi = tid; fi < 1024; fi += TPB) {
                int di = fi >> 3, lq = fi & 7;
                float4 val = __ldcg((const float4*)(ctxin +
                    ((size_t)b * HH + dc + di) * LL + l0 + lq * 4));
                *(float4*)&xs[di * 36 + lq * 4] = val;
            }
            __syncthreads();

            const float* wrow = Wc + (size_t)tid * HH + dc;
            for (int d4 = 0; d4 < 128; d4 += 4) {
                float4 wq = *(const float4*)(wrow + d4);
                float wv[4] = {wq.x, wq.y, wq.z, wq.w};
#pragma unroll
                for (int j = 0; j < 4; j++) {
                    float2 ws = make_float2(wv[j], wv[j]);
                    const float2* srow = (const float2*)&xs[(d4 + j) * 36];
#pragma unroll
                    for (int p = 0; p < 16; p++) ffma2(acc[p], ws, srow[p]);
                }
            }
        }
        float bcv = bc[tid];
#pragma unroll
        for (int p = 0; p < 16; p++) {
            size_t base = ((size_t)b * LL + l0 + 2 * p) * HH + tid;
            g_ctx[base] = acc[p].x + bcv;
            g_ctx[base + HH] = acc[p].y + bcv;
        }
    }
    gbar(++ep);

    // ======== step loop ========
    for (int t = 0; t < LL; t++) {
        // ---- Phase A: gates GEMM (f32x2) + LSTM cell ----
#pragma unroll 1
        for (int sub = 0; sub < 2; sub++) {
            int vt = blk + sub * GRID;
            int it = vt & 63, bt = vt >> 6;
            int ibase = it * 8, bbase = bt * 16;
            __syncthreads();
            {
                const float4* src = (const float4*)(g_h + bbase * HH);
                float4* dst = (float4*)xs;
                for (int idx = tid; idx < 16 * 512 / 4; idx += TPB)
                    dst[idx] = __ldcg(src + idx);
            }
            __syncthreads();

            int i = ibase + (w >> 1);
            int bh = (w & 1) * 8;
            const float* wr0 = Whh + (size_t)(0 * HH + i) * HH;
            const float* wr1 = Whh + (size_t)(1 * HH + i) * HH;
            const float* wr2 = Whh + (size_t)(2 * HH + i) * HH;
            const float* wr3 = Whh + (size_t)(3 * HH + i) * HH;

            float2 acc[4][8];
#pragma unroll
            for (int g = 0; g < 4; g++)
#pragma unroll
                for (int b = 0; b < 8; b++) acc[g][b] = make_float2(0.f, 0.f);

            float2 c0v = *(const float2*)(wr0 + lane * 2);
            float2 c1v = *(const float2*)(wr1 + lane * 2);
            float2 c2v = *(const float2*)(wr2 + lane * 2);
            float2 c3v = *(const float2*)(wr3 + lane * 2);
#pragma unroll
            for (int kk = 0; kk < 8; kk++) {
                float2 n0, n1, n2, n3;
                if (kk < 7) {
                    int kn = (kk + 1) * 64 + lane * 2;
                    n0 = *(const float2*)(wr0 + kn);
                    n1 = *(const float2*)(wr1 + kn);
                    n2 = *(const float2*)(wr2 + kn);
                    n3 = *(const float2*)(wr3 + kn);
                }
                int k = kk * 64 + lane * 2;
#pragma unroll
                for (int b = 0; b < 8; b++) {
                    float2 hv = *(const float2*)&xs[(bh + b) * 512 + k];
                    ffma2(acc[0][b], c0v, hv);
                    ffma2(acc[1][b], c1v, hv);
                    ffma2(acc[2][b], c2v, hv);
                    ffma2(acc[3][b], c3v, hv);
                }
                if (kk < 7) { c0v = n0; c1v = n1; c2v = n2; c3v = n3; }
            }

            float gate[4] = {0.f, 0.f, 0.f, 0.f};
#pragma unroll
            for (int g = 0; g < 4; g++)
#pragma unroll
                for (int b = 0; b < 8; b++) {
                    float vv = wsum(acc[g][b].x + acc[g][b].y);
                    if (lane == b) gate[g] = vv;
                }

            if (lane < 8) {
                int b = bbase + bh + lane;
                float ig = gate[0] + bhh[0 * HH + i];
                float fg = gate[1] + bhh[1 * HH + i];
                float gg = gate[2] + bhh[2 * HH + i];
                float og = gate[3] + bhh[3 * HH + i];
                float c_old = g_c[b * HH + i];
                float si = 1.f / (1.f + expf(-ig));
                float sf = 1.f / (1.f + expf(-fg));
                float so = 1.f / (1.f + expf(-og));
                float ct = sf * c_old + si * tanhf(gg);
                float ht = so * tanhf(ct);
                g_c[b * HH + i] = ct;
                g_cat[b * 2 * HH + HH + i] = ht;
            }
        }
        gbar(++ep);

        // ---- Phase B: inp = W_in * h_t + b_in (f32x2) ----
        {
            int rt = blk & 15, bt = blk >> 4;
            int bbase = bt * 8, r0 = rt * 32 + w * 2;
            for (int idx = tid; idx < 8 * 128; idx += TPB) {
                int b = idx >> 7, j = idx & 127;
                ((float4*)xs)[b * 128 + j] =
                    __ldcg((const float4*)(g_cat + (size_t)(bbase + b) * 2 * HH + HH) + j);
            }
            __syncthreads();

            const float* w0 = Win + (size_t)r0 * HH;
            const float* w1 = Win + (size_t)(r0 + 1) * HH;
            float2 acc[2][8];
#pragma unroll
            for (int r = 0; r < 2; r++)
#pragma unroll
                for (int b = 0; b < 8; b++) acc[r][b] = make_float2(0.f, 0.f);

            float2 a0 = *(const float2*)(w0 + lane * 2);
            float2 a1 = *(const float2*)(w1 + lane * 2);
#pragma unroll
            for (int kk = 0; kk < 8; kk++) {
                float2 na0, na1;
                if (kk < 7) {
                    int kn = (kk + 1) * 64 + lane * 2;
                    na0 = *(const float2*)(w0 + kn);
                    na1 = *(const float2*)(w1 + kn);
                }
                int k = kk * 64 + lane * 2;
#pragma unroll
                for (int b = 0; b < 8; b++) {
                    float2 xv = *(const float2*)&xs[b * 512 + k];
                    ffma2(acc[0][b], a0, xv);
                    ffma2(acc[1][b], a1, xv);
                }
                if (kk < 7) { a0 = na0; a1 = na1; }
            }

            float res[2] = {0.f, 0.f};
#pragma unroll
            for (int r = 0; r < 2; r++)
#pragma unroll
                for (int b = 0; b < 8; b++) {
                    float vv = wsum(acc[r][b].x + acc[r][b].y);
                    if (lane == b) res[r] = vv;
                }
            if (lane < 8) {
#pragma unroll
                for (int r = 0; r < 2; r++)
                    g_inp[(size_t)(bbase + lane) * HH + r0 + r] = res[r] + bin[r0 + r];
            }
        }
        gbar(++ep);

        // ---- Phase C1: scores (cluster pair: 2 blocks per batch, 64 l each) ----
        {
            int b = blk >> 1, half = blk & 1;
            sm_inp[tid] = __ldcg(&g_inp[b * HH + tid]);
            __syncthreads();

            float inpv[16], Vv[16];
#pragma unroll
            for (int m = 0; m < 16; m++) {
                inpv[m] = sm_inp[m * 32 + lane];
                Vv[m] = V[m * 32 + lane];
            }
#pragma unroll
            for (int li = 0; li < 4; li++) {
                int l = half * 64 + w * 4 + li;
                const float* cp = g_ctx + ((size_t)b * LL + l) * HH + lane;
                float s = 0.f;
#pragma unroll
                for (int m = 0; m < 16; m++) {
                    float cv = __ldcg(cp + m * 32);
                    s += Vv[m] * fast_tanh(inpv[m] + cv);
                }
                s = wsum(s);
                if (lane == 0) g_sc[b * LL + l] = s;
            }
        }
        csync();   // pair-local: both halves' scores visible

        // ---- Phase C2: softmax + argmax + hid (pair of blocks per batch) ----
        {
            int b = blk >> 1, half = blk & 1;
            if (tid < LL) {
                sm_sc[tid] = __ldcg(&g_sc[b * LL + tid]);
                sm_mask[tid] = __ldcg(&g_mask[b * LL + tid]);
            }
            __syncthreads();

            if (w == 0) {
                float sv[4], mk[4];
#pragma unroll
                for (int j = 0; j < 4; j++) {
                    mk[j] = sm_mask[lane + 32 * j];
                    sv[j] = (mk[j] != 0.f) ? sm_sc[lane + 32 * j] : -3.4e38f;
                }
                float m = fmaxf(fmaxf(sv[0], sv[1]), fmaxf(sv[2], sv[3]));
#pragma unroll
                for (int off = 16; off; off >>= 1)
                    m = fmaxf(m, __shfl_xor_sync(0xffffffffu, m, off));

                float e[4], sum = 0.f;
#pragma unroll
                for (int j = 0; j < 4; j++) {
                    e[j] = (mk[j] != 0.f) ? expf(sv[j] - m) : 0.f;
                    sum += e[j];
                }
                sum = wsum(sum);
                float inv = 1.f / sum;

                float best = -1.f;
                int bidx = 0;
#pragma unroll
                for (int j = 0; j < 4; j++) {
                    int l = lane + 32 * j;
                    float a = e[j] * inv;
                    sm_alpha[l] = a;
                    if (half == 0)
                        out[(size_t)b * LL * LL + (size_t)t * LL + l] = a;
                    float cand = (mk[j] != 0.f) ? a : -1.f;
                    if (cand > best) { best = cand; bidx = l; }
                }
#pragma unroll
                for (int off = 16; off; off >>= 1) {
                    float ob = __shfl_xor_sync(0xffffffffu, best, off);
                    int oi = __shfl_xor_sync(0xffffffffu, bidx, off);
                    if (ob > best || (ob == best && oi < bidx)) { best = ob; bidx = oi; }
                }
                if (half == 0 && lane == 0) {
                    out[OUT_PTR + b * LL + t] = (float)bidx;
                    g_bidx[b] = bidx;
                }
            }
            __syncthreads();

            {
                int lh = tid >> 8;
                int hh = half * 256 + (tid & 255);
                const float* cp = g_ctx + (size_t)b * LL * HH + (size_t)(lh * 64) * HH + hh;
                float a = 0.f;
#pragma unroll 8
                for (int l = 0; l < 64; l++)
                    a += __ldcg(cp + (size_t)l * HH) * sm_alpha[lh * 64 + l];
                sm_part[tid] = a;
            }
            __syncthreads();
            if (tid < 256)
                g_cat[b * 2 * HH + half * 256 + tid] = sm_part[tid] + sm_part[256 + tid];
        }
        gbar(++ep);

        // ---- Phase D: h = tanh(W_out * [hid, h_t] + b_out) + mask update ----
        {
            if (blk == 0 && tid < BB)
                g_mask[tid * LL + __ldcg(&g_bidx[tid])] = 0.f;

            int rt = blk & 15, bt = blk >> 4;
            int bbase = bt * 8, r0 = rt * 32 + w * 2;
            {
                const float4* src = (const float4*)(g_cat + (size_t)bbase * 2 * HH);
                float4* dst = (float4*)xs;
                for (int idx = tid; idx < 8 * 1024 / 4; idx += TPB)
                    dst[idx] = __ldcg(src + idx);
            }
            __syncthreads();

            const float* w0 = Wout + (size_t)r0 * 2 * HH;
            const float* w1 = Wout + (size_t)(r0 + 1) * 2 * HH;
            float2 acc[2][8];
#pragma unroll
            for (int r = 0; r < 2; r++)
#pragma unroll
                for (int b = 0; b < 8; b++) acc[r][b] = make_float2(0.f, 0.f);

            float2 a0 = *(const float2*)(w0 + lane * 2);
            float2 a1 = *(const float2*)(w1 + lane * 2);
#pragma unroll
            for (int kk = 0; kk < 16; kk++) {
                float2 na0, na1;
                if (kk < 15) {
                    int kn = (kk + 1) * 64 + lane * 2;
                    na0 = *(const float2*)(w0 + kn);
                    na1 = *(const float2*)(w1 + kn);
                }
                int k = kk * 64 + lane * 2;
#pragma unroll
                for (int b = 0; b < 8; b++) {
                    float2 xv = *(const float2*)&xs[b * 1024 + k];
                    ffma2(acc[0][b], a0, xv);
                    ffma2(acc[1][b], a1, xv);
                }
                if (kk < 15) { a0 = na0; a1 = na1; }
            }

            float res[2] = {0.f, 0.f};
#pragma unroll
            for (int r = 0; r < 2; r++)
#pragma unroll
                for (int b = 0; b < 8; b++) {
                    float vv = wsum(acc[r][b].x + acc[r][b].y);
                    if (lane == b) res[r] = vv;
                }
            if (lane < 8) {
#pragma unroll
                for (int r = 0; r < 2; r++)
                    g_h[(size_t)(bbase + lane) * HH + r0 + r] =
                        tanhf(res[r] + bout[r0 + r]);
            }
        }
        gbar(++ep);
    }

    // final h/c copy
    for (int i = blk * TPB + tid; i < BB * HH; i += GRID * TPB) {
        out[OUT_H + i] = g_h[i];
        out[OUT_C + i] = g_c[i];
    }
}

extern "C" void kernel_launch(void* const* d_in, const int* in_sizes, int n_in,
                              void* d_out, int out_size) {
    const float* h0   = (const float*)d_in[2];
    const float* c0   = (const float*)d_in[3];
    const float* ctxi = (const float*)d_in[4];
    const float* Whh  = (const float*)d_in[5];
    const float* bhh  = (const float*)d_in[6];
    const float* Win  = (const float*)d_in[7];
    const float* bin  = (const float*)d_in[8];
    const float* Wc   = (const float*)d_in[9];
    const float* bc   = (const float*)d_in[10];
    const float* V    = (const float*)d_in[11];
    const float* Wout = (const float*)d_in[12];
    const float* bout = (const float*)d_in[13];
    float* out = (float*)d_out;

    k_all<<<GRID, TPB>>>(h0, c0, ctxi, Wc, bc, Whh, bhh,
                         Win, bin, Wout, bout, V, out);
}